// round 3
// baseline (speedup 1.0000x reference)
#include <cuda_runtime.h>
#include <cstdint>

#define RV_NUM 10
#define RV_LEN 128
#define BZ     32
#define NREV   (BZ * RV_NUM)      // 320 reviews
#define ROWS   (NREV * RV_LEN)    // 40960 tokens per tensor
#define KD     300                // in_feat
#define ND     128                // out_feat / hdim
#define MTOK   (RV_NUM * RV_LEN)  // 1280 tokens per sample

// Scratch: transformed features and per-batch means. __device__ globals (no allocs).
__device__ float g_t[2][ROWS * ND];     // [0]=ta, [1]=tb   (~42 MB total, L2-resident)
__device__ float g_mean[2][BZ * ND];    // per-batch mean of ta / tb over all 1280 tokens

// ---------------------------------------------------------------------------
// Packed f32x2 helpers (Blackwell double-rate fp32). ptxas will NOT auto-fuse
// FFMA2 from C++; must come from PTX fma.rn.f32x2.
// ---------------------------------------------------------------------------
__device__ __forceinline__ uint64_t pack2(float x) {
    uint64_t r;
    asm("mov.b64 %0, {%1, %1};" : "=l"(r) : "r"(__float_as_uint(x)));
    return r;
}
__device__ __forceinline__ void ffma2(uint64_t& d, uint64_t a, uint64_t b) {
    asm("fma.rn.f32x2 %0, %1, %2, %0;" : "+l"(d) : "l"(a), "l"(b));
}

// ---------------------------------------------------------------------------
// Kernel 1: T = relu(X @ W + b) for X = seq_a (y=0) or seq_b (y=1).
// C[40960,128] = A[40960,300] @ W[300,128].  BM=128, BN=128, BK=20, 256 thr,
// 8x8 per-thread tile held as 8x4 packed f32x2 accumulators.
// ---------------------------------------------------------------------------
#define BM 128
#define BN 128
#define BK 20
#define TM 8
#define TN 8

__global__ __launch_bounds__(256) void gemm_relu_kernel(
    const float* __restrict__ A0, const float* __restrict__ A1,
    const float* __restrict__ W,  const float* __restrict__ bias)
{
    const int which = blockIdx.y;
    const float* __restrict__ A = which ? A1 : A0;
    float* __restrict__ C = g_t[which];

    __shared__ float As[BK][132];   // transposed A tile, padded (132%32=4 spreads store banks)
    __shared__ float Bs[BK][BN];

    const int tid = threadIdx.x;
    const int tx  = tid & 15;       // 16 col groups of 8
    const int ty  = tid >> 4;       // 16 row groups of 8
    const int rowBase = blockIdx.x * BM;

    uint64_t acc[TM][TN / 2];
    #pragma unroll
    for (int i = 0; i < TM; i++)
        #pragma unroll
        for (int j = 0; j < TN / 2; j++) acc[i][j] = 0ULL;

    for (int t = 0; t < KD / BK; ++t) {
        const int k0 = t * BK;
        // A tile: 128 rows x 20 k-vals = 640 float4 (rows are float4-aligned: 300*4%16==0)
        for (int i = tid; i < (BM * BK / 4); i += 256) {
            int r = i / (BK / 4);          // row in tile
            int q = i % (BK / 4);          // which float4 along k
            float4 v = *(const float4*)(A + (size_t)(rowBase + r) * KD + k0 + q * 4);
            As[q * 4 + 0][r] = v.x;
            As[q * 4 + 1][r] = v.y;
            As[q * 4 + 2][r] = v.z;
            As[q * 4 + 3][r] = v.w;
        }
        // W tile: 20 x 128 = 640 float4
        for (int i = tid; i < (BK * BN / 4); i += 256) {
            int k = i / (BN / 4);
            int c = i % (BN / 4);
            *(float4*)&Bs[k][c * 4] = *(const float4*)(W + (size_t)(k0 + k) * ND + c * 4);
        }
        __syncthreads();

        #pragma unroll
        for (int k = 0; k < BK; ++k) {
            float4 a0 = *(const float4*)&As[k][ty * TM];
            float4 a1 = *(const float4*)&As[k][ty * TM + 4];
            double2 bq0 = *(const double2*)&Bs[k][tx * TN];
            double2 bq1 = *(const double2*)&Bs[k][tx * TN + 4];
            uint64_t bv[4];
            bv[0] = (uint64_t)__double_as_longlong(bq0.x);
            bv[1] = (uint64_t)__double_as_longlong(bq0.y);
            bv[2] = (uint64_t)__double_as_longlong(bq1.x);
            bv[3] = (uint64_t)__double_as_longlong(bq1.y);
            float av[TM] = {a0.x, a0.y, a0.z, a0.w, a1.x, a1.y, a1.z, a1.w};
            #pragma unroll
            for (int i = 0; i < TM; i++) {
                uint64_t a2 = pack2(av[i]);
                #pragma unroll
                for (int j = 0; j < TN / 2; j++) ffma2(acc[i][j], a2, bv[j]);
            }
        }
        __syncthreads();
    }

    // Epilogue: + bias, ReLU, store.
    const int c0 = tx * TN;
    float bl[TN];
    #pragma unroll
    for (int j = 0; j < TN; j++) bl[j] = bias[c0 + j];
    #pragma unroll
    for (int i = 0; i < TM; i++) {
        const int row = rowBase + ty * TM + i;
        float v[TN];
        #pragma unroll
        for (int j = 0; j < TN / 2; j++) {
            v[2 * j + 0] = __uint_as_float((unsigned)(acc[i][j] & 0xffffffffULL));
            v[2 * j + 1] = __uint_as_float((unsigned)(acc[i][j] >> 32));
        }
        float4 o0, o1;
        o0.x = fmaxf(v[0] + bl[0], 0.f); o0.y = fmaxf(v[1] + bl[1], 0.f);
        o0.z = fmaxf(v[2] + bl[2], 0.f); o0.w = fmaxf(v[3] + bl[3], 0.f);
        o1.x = fmaxf(v[4] + bl[4], 0.f); o1.y = fmaxf(v[5] + bl[5], 0.f);
        o1.z = fmaxf(v[6] + bl[6], 0.f); o1.w = fmaxf(v[7] + bl[7], 0.f);
        *(float4*)(C + (size_t)row * ND + c0)     = o0;
        *(float4*)(C + (size_t)row * ND + c0 + 4) = o1;
    }
}

// ---------------------------------------------------------------------------
// Kernel 2: per-batch mean over all 1280 tokens: g_mean[w][b][d].
// grid (32, 2), 1024 threads: 8 m-chunks x 128 dims, smem tree reduce.
// ---------------------------------------------------------------------------
__global__ __launch_bounds__(1024) void mean_kernel()
{
    const int which = blockIdx.y;
    const int b     = blockIdx.x;
    const int d     = threadIdx.x & 127;
    const int chunk = threadIdx.x >> 7;   // 0..7, 160 tokens each

    const float* base = g_t[which] + ((size_t)b * MTOK + chunk * 160) * ND + d;
    float s = 0.f;
    #pragma unroll 8
    for (int m = 0; m < 160; m++) s += base[(size_t)m * ND];

    __shared__ float red[8][128];
    red[chunk][d] = s;
    __syncthreads();
    if (chunk == 0) {
        float t = 0.f;
        #pragma unroll
        for (int c = 0; c < 8; c++) t += red[c][d];
        g_mean[which][b * ND + d] = t * (1.0f / (float)MTOK);
    }
}

// ---------------------------------------------------------------------------
// Kernel 3: per review n: scores = sa . mean(other), masked softmax, weighted
// sum. Tile staged in smem with stride 129 -> both row reads (scores, thread=l)
// and column reads (output, thread=d) are bank-conflict-free.
// ---------------------------------------------------------------------------
#define TSTRIDE 129
#define ATTN_SMEM (128 * TSTRIDE * 4)

__global__ __launch_bounds__(128) void attn_kernel(
    const int* __restrict__ mask_a, const int* __restrict__ mask_b,
    float* __restrict__ out)
{
    extern __shared__ float tile[];                 // [128][129]
    __shared__ float meanv[128], wv[128], red[8];

    const int side = blockIdx.y;                    // 0: a-side, 1: b-side
    const int n    = blockIdx.x;                    // review index 0..319
    const int b    = n / RV_NUM;
    const int tid  = threadIdx.x;                   // 128 threads
    const int lane = tid & 31, wid = tid >> 5;

    const float* __restrict__ T = g_t[side] + (size_t)n * RV_LEN * ND;
    const int*   __restrict__ mask = side ? mask_b : mask_a;

    meanv[tid] = g_mean[side ^ 1][b * ND + tid];    // other side's mean

    // coalesced load, conflict-free padded store
    for (int i = tid; i < RV_LEN * ND; i += 128) {
        int l = i >> 7, d = i & 127;
        tile[l * TSTRIDE + d] = T[i];
    }
    __syncthreads();

    // scores: thread = token l
    float s = 0.f;
    #pragma unroll 8
    for (int d = 0; d < ND; d++) s += tile[tid * TSTRIDE + d] * meanv[d];

    float logit = (mask[n * RV_LEN + tid] > 0) ? s : -1e9f;

    // block max
    float v = logit;
    #pragma unroll
    for (int o = 16; o; o >>= 1) v = fmaxf(v, __shfl_xor_sync(0xffffffffu, v, o));
    if (lane == 0) red[wid] = v;
    __syncthreads();
    const float gmax = fmaxf(fmaxf(red[0], red[1]), fmaxf(red[2], red[3]));

    const float e = __expf(logit - gmax);
    v = e;
    #pragma unroll
    for (int o = 16; o; o >>= 1) v += __shfl_xor_sync(0xffffffffu, v, o);
    if (lane == 0) red[4 + wid] = v;
    __syncthreads();
    const float gsum = red[4] + red[5] + red[6] + red[7];

    const float w = e / gsum;
    wv[tid] = w;
    out[(size_t)(2 + side) * ROWS + (size_t)n * RV_LEN + tid] = w;   // atob_w / btoa_w
    __syncthreads();

    // weighted sum: thread = dim d
    float acc = 0.f;
    #pragma unroll 8
    for (int l = 0; l < RV_LEN; l++) acc += wv[l] * tile[l * TSTRIDE + tid];
    out[(size_t)side * ROWS + (size_t)n * ND + tid] = acc;           // a_out / b_out
}

// ---------------------------------------------------------------------------
extern "C" void kernel_launch(void* const* d_in, const int* in_sizes, int n_in,
                              void* d_out, int out_size)
{
    const float* seq_a  = (const float*)d_in[0];
    const float* seq_b  = (const float*)d_in[1];
    const int*   mask_a = (const int*)d_in[2];
    const int*   mask_b = (const int*)d_in[3];
    const float* W      = (const float*)d_in[4];
    const float* bias   = (const float*)d_in[5];
    float* out = (float*)d_out;

    cudaFuncSetAttribute(attn_kernel, cudaFuncAttributeMaxDynamicSharedMemorySize, ATTN_SMEM);

    dim3 g1(ROWS / BM, 2);
    gemm_relu_kernel<<<g1, 256>>>(seq_a, seq_b, W, bias);

    dim3 g2(BZ, 2);
    mean_kernel<<<g2, 1024>>>();

    dim3 g3(NREV, 2);
    attn_kernel<<<g3, 128, ATTN_SMEM>>>(mask_a, mask_b, out);
}

// round 5
// speedup vs baseline: 1.8594x; 1.8594x over previous
#include <cuda_runtime.h>
#include <cuda_bf16.h>
#include <cstdint>

#define RV_NUM 10
#define RV_LEN 128
#define BZ     32
#define NREV   (BZ * RV_NUM)      // 320 reviews
#define ROWS   (NREV * RV_LEN)    // 40960 tokens per tensor
#define KD     300                // in_feat
#define KPAD   320                // padded K (multiple of 32)
#define ND     128                // out_feat / hdim
#define MTOK   (RV_NUM * RV_LEN)  // 1280 tokens per sample

// Scratch (no runtime allocs): transformed features, means, split W.
__device__ float g_t[2][ROWS * ND];          // ta / tb (~42 MB)
__device__ float g_mean[2][BZ * ND];
__device__ __nv_bfloat16 g_wt_hi[ND * KPAD]; // W^T hi  [n][k]
__device__ __nv_bfloat16 g_wt_lo[ND * KPAD]; // W^T lo

// ---------------------------------------------------------------------------
// PTX helpers (sm_103 base target: NO tcgen05; use mma.sync / ldmatrix / cp.async)
// ---------------------------------------------------------------------------
__device__ __forceinline__ uint32_t smem_u32(const void* p) {
    uint32_t a;
    asm("{ .reg .u64 t; cvta.to.shared.u64 t, %1; cvt.u32.u64 %0, t; }"
        : "=r"(a) : "l"(p));
    return a;
}
__device__ __forceinline__ void cp_async16(uint32_t dst, const void* src) {
    asm volatile("cp.async.cg.shared.global [%0], [%1], 16;"
                 :: "r"(dst), "l"(src) : "memory");
}
__device__ __forceinline__ void cp_commit() {
    asm volatile("cp.async.commit_group;" ::: "memory");
}
__device__ __forceinline__ void cp_wait0() {
    asm volatile("cp.async.wait_group 0;" ::: "memory");
}
__device__ __forceinline__ void ldmx4(uint32_t addr, uint32_t r[4]) {
    asm volatile("ldmatrix.sync.aligned.m8n8.x4.shared.b16 {%0,%1,%2,%3}, [%4];"
                 : "=r"(r[0]), "=r"(r[1]), "=r"(r[2]), "=r"(r[3]) : "r"(addr));
}
__device__ __forceinline__ void mma16816(float d[4], const uint32_t a[4],
                                         uint32_t b0, uint32_t b1) {
    asm volatile(
        "mma.sync.aligned.m16n8k16.row.col.f32.bf16.bf16.f32 "
        "{%0,%1,%2,%3}, {%4,%5,%6,%7}, {%8,%9}, {%0,%1,%2,%3};"
        : "+f"(d[0]), "+f"(d[1]), "+f"(d[2]), "+f"(d[3])
        : "r"(a[0]), "r"(a[1]), "r"(a[2]), "r"(a[3]), "r"(b0), "r"(b1));
}

// ---------------------------------------------------------------------------
// Kernel 0: split + transpose W [300,128] f32 -> Wt_hi/Wt_lo [128,320] bf16
// ---------------------------------------------------------------------------
__global__ __launch_bounds__(256) void prep_w_kernel(const float* __restrict__ W)
{
    int gid = blockIdx.x * 256 + threadIdx.x;   // 160 * 256 = 40960
    int n = gid / KPAD, k = gid % KPAD;
    float v = (k < KD) ? W[k * ND + n] : 0.f;
    __nv_bfloat16 h = __float2bfloat16(v);
    float lo = v - __bfloat162float(h);
    g_wt_hi[gid] = h;
    g_wt_lo[gid] = __float2bfloat16(lo);
}

// ---------------------------------------------------------------------------
// Kernel 1: HMMA GEMM  T = relu(X @ W + b), split-bf16 (hi/lo), fp32 accum.
// Grid (320, 2), 256 threads: 8 warps as 2(m) x 4(n), warp tile 64x32.
// ---------------------------------------------------------------------------
#define BK 32
#define NCHUNK (KPAD / BK)            // 10
#define RS 40                         // bf16 per smem row (80B: conflict-free ldmatrix)
#define AHI_OFF 0
#define ALO_OFF (128 * RS * 2)        // 10240
#define BHI_OFF (2 * 128 * RS * 2)    // 20480
#define BLO_OFF (3 * 128 * RS * 2)    // 30720
#define STAGE_BYTES (4 * 128 * RS * 2)// 40960
#define GEMM_SMEM (2 * STAGE_BYTES)   // 81920

__device__ __forceinline__ void compute_stage(
    uint32_t stgc, int wm, int wn, int lrow, int lk, float acc[4][4][4])
{
    #pragma unroll
    for (int ks = 0; ks < 2; ++ks) {
        uint32_t ah[4][4], al[4][4], bh[4][2], bl[4][2];
        #pragma unroll
        for (int mf = 0; mf < 4; ++mf) {
            uint32_t ad = stgc + AHI_OFF
                        + ((uint32_t)(wm * 64 + mf * 16 + lrow) * RS + ks * 16 + lk) * 2;
            ldmx4(ad, ah[mf]);
            ldmx4(ad + (ALO_OFF - AHI_OFF), al[mf]);
        }
        #pragma unroll
        for (int p = 0; p < 2; ++p) {
            uint32_t bd = stgc + BHI_OFF
                        + ((uint32_t)(wn * 32 + p * 16 + lrow) * RS + ks * 16 + lk) * 2;
            uint32_t r[4];
            ldmx4(bd, r);
            bh[2 * p][0] = r[0]; bh[2 * p + 1][0] = r[1];
            bh[2 * p][1] = r[2]; bh[2 * p + 1][1] = r[3];
            ldmx4(bd + (BLO_OFF - BHI_OFF), r);
            bl[2 * p][0] = r[0]; bl[2 * p + 1][0] = r[1];
            bl[2 * p][1] = r[2]; bl[2 * p + 1][1] = r[3];
        }
        #pragma unroll
        for (int mf = 0; mf < 4; ++mf)
            #pragma unroll
            for (int nf = 0; nf < 4; ++nf) {
                mma16816(acc[mf][nf], ah[mf], bh[nf][0], bh[nf][1]);
                mma16816(acc[mf][nf], al[mf], bh[nf][0], bh[nf][1]);
                mma16816(acc[mf][nf], ah[mf], bl[nf][0], bl[nf][1]);
            }
    }
}

__global__ __launch_bounds__(256) void gemm_mma_kernel(
    const float* __restrict__ A0, const float* __restrict__ A1,
    const float* __restrict__ bias)
{
    extern __shared__ char smem[];
    const uint32_t sb = smem_u32(smem);
    const int tid = threadIdx.x, wid = tid >> 5, lid = tid & 31;
    const int side = blockIdx.y;
    const int rowBase = blockIdx.x * 128;
    const float* __restrict__ A = side ? A1 : A0;

    const int wm = wid >> 2, wn = wid & 3;       // warp grid 2 x 4
    const int g = lid >> 3, lr = lid & 7;
    const int lrow = (g & 1) * 8 + lr;           // ldmatrix row within 16-frag
    const int lk   = (g >> 1) * 8;               // ldmatrix k offset within 16

    float acc[4][4][4];
    #pragma unroll
    for (int i = 0; i < 4; ++i)
        #pragma unroll
        for (int j = 0; j < 4; ++j)
            #pragma unroll
            for (int q = 0; q < 4; ++q) acc[i][j][q] = 0.f;

    // A loader: thread covers row=tid/2, k-half=tid%2 (16 floats = 4 float4)
    const int arow = tid >> 1, ahalf = tid & 1;
    const float* agp = A + (size_t)(rowBase + arow) * KD + ahalf * 16;
    // B loader: thread covers half=tid/128 (hi/lo), n=tid%128, 32 k = 4 x 16B
    const int bhalf = tid >> 7, bn = tid & 127;
    const __nv_bfloat16* bgp = (bhalf ? g_wt_lo : g_wt_hi) + (size_t)bn * KPAD;
    const uint32_t bdst0 = sb + (bhalf ? BLO_OFF : BHI_OFF) + (uint32_t)bn * RS * 2;

    float4 apref[4];

    for (int c = 0; c < NCHUNK; ++c) {
        const int k0 = c * BK;
        const uint32_t stg_off = (uint32_t)(c & 1) * STAGE_BYTES;

        // prefetch A (global -> regs)
        #pragma unroll
        for (int q = 0; q < 4; ++q) {
            int kb = k0 + ahalf * 16 + q * 4;
            apref[q] = (kb < KD) ? *(const float4*)(agp + k0 + q * 4)
                                 : make_float4(0.f, 0.f, 0.f, 0.f);
        }
        // prefetch B (global -> smem, async; already bf16)
        #pragma unroll
        for (int q = 0; q < 4; ++q)
            cp_async16(bdst0 + stg_off + q * 16, bgp + k0 + q * 8);
        cp_commit();

        if (c > 0) compute_stage(sb + (uint32_t)((c - 1) & 1) * STAGE_BYTES,
                                 wm, wn, lrow, lk, acc);

        // convert + store A hi/lo
        {
            uint32_t off = stg_off + AHI_OFF + ((uint32_t)arow * RS + ahalf * 16) * 2;
            #pragma unroll
            for (int q = 0; q < 4; ++q) {
                float4 v = apref[q];
                __nv_bfloat162 h01 = __floats2bfloat162_rn(v.x, v.y);
                __nv_bfloat162 h23 = __floats2bfloat162_rn(v.z, v.w);
                __nv_bfloat162 l01 = __floats2bfloat162_rn(v.x - __low2float(h01),
                                                           v.y - __high2float(h01));
                __nv_bfloat162 l23 = __floats2bfloat162_rn(v.z - __low2float(h23),
                                                           v.w - __high2float(h23));
                *(uint2*)(smem + off + q * 8) =
                    make_uint2(*(uint32_t*)&h01, *(uint32_t*)&h23);
                *(uint2*)(smem + off + (ALO_OFF - AHI_OFF) + q * 8) =
                    make_uint2(*(uint32_t*)&l01, *(uint32_t*)&l23);
            }
        }
        cp_wait0();
        __syncthreads();
    }
    compute_stage(sb + (uint32_t)((NCHUNK - 1) & 1) * STAGE_BYTES,
                  wm, wn, lrow, lk, acc);

    // Epilogue: bias + ReLU, fragment regs -> global
    const int trow = lid >> 2, tcol = (lid & 3) * 2;
    float bcol[4][2];
    #pragma unroll
    for (int nf = 0; nf < 4; ++nf) {
        bcol[nf][0] = __ldg(bias + wn * 32 + nf * 8 + tcol);
        bcol[nf][1] = __ldg(bias + wn * 32 + nf * 8 + tcol + 1);
    }
    float* Cb = g_t[side];
    #pragma unroll
    for (int mf = 0; mf < 4; ++mf) {
        const int r0 = rowBase + wm * 64 + mf * 16 + trow;
        #pragma unroll
        for (int nf = 0; nf < 4; ++nf) {
            const int c0 = wn * 32 + nf * 8 + tcol;
            float2 v0, v1;
            v0.x = fmaxf(acc[mf][nf][0] + bcol[nf][0], 0.f);
            v0.y = fmaxf(acc[mf][nf][1] + bcol[nf][1], 0.f);
            v1.x = fmaxf(acc[mf][nf][2] + bcol[nf][0], 0.f);
            v1.y = fmaxf(acc[mf][nf][3] + bcol[nf][1], 0.f);
            *(float2*)(Cb + (size_t)r0 * ND + c0)       = v0;
            *(float2*)(Cb + (size_t)(r0 + 8) * ND + c0) = v1;
        }
    }
}

// ---------------------------------------------------------------------------
// Kernel 2: per-batch mean over all 1280 tokens
// ---------------------------------------------------------------------------
__global__ __launch_bounds__(1024) void mean_kernel()
{
    const int which = blockIdx.y;
    const int b     = blockIdx.x;
    const int d     = threadIdx.x & 127;
    const int chunk = threadIdx.x >> 7;

    const float* base = g_t[which] + ((size_t)b * MTOK + chunk * 160) * ND + d;
    float s = 0.f;
    #pragma unroll 8
    for (int m = 0; m < 160; m++) s += base[(size_t)m * ND];

    __shared__ float red[8][128];
    red[chunk][d] = s;
    __syncthreads();
    if (chunk == 0) {
        float t = 0.f;
        #pragma unroll
        for (int c = 0; c < 8; c++) t += red[c][d];
        g_mean[which][b * ND + d] = t * (1.0f / (float)MTOK);
    }
}

// ---------------------------------------------------------------------------
// Kernel 3: masked-softmax attention per review
// ---------------------------------------------------------------------------
#define TSTRIDE 129
#define ATTN_SMEM (128 * TSTRIDE * 4)

__global__ __launch_bounds__(128) void attn_kernel(
    const int* __restrict__ mask_a, const int* __restrict__ mask_b,
    float* __restrict__ out)
{
    extern __shared__ float tile[];                 // [128][129]
    __shared__ float meanv[128], wv[128], red[8];

    const int side = blockIdx.y;
    const int n    = blockIdx.x;
    const int b    = n / RV_NUM;
    const int tid  = threadIdx.x;
    const int lane = tid & 31, wid = tid >> 5;

    const float* __restrict__ T = g_t[side] + (size_t)n * RV_LEN * ND;
    const int*   __restrict__ mask = side ? mask_b : mask_a;

    meanv[tid] = g_mean[side ^ 1][b * ND + tid];

    for (int i = tid; i < RV_LEN * ND; i += 128) {
        int l = i >> 7, d = i & 127;
        tile[l * TSTRIDE + d] = T[i];
    }
    __syncthreads();

    float s = 0.f;
    #pragma unroll 8
    for (int d = 0; d < ND; d++) s += tile[tid * TSTRIDE + d] * meanv[d];

    float logit = (mask[n * RV_LEN + tid] > 0) ? s : -1e9f;

    float v = logit;
    #pragma unroll
    for (int o = 16; o; o >>= 1) v = fmaxf(v, __shfl_xor_sync(0xffffffffu, v, o));
    if (lane == 0) red[wid] = v;
    __syncthreads();
    const float gmax = fmaxf(fmaxf(red[0], red[1]), fmaxf(red[2], red[3]));

    const float e = __expf(logit - gmax);
    v = e;
    #pragma unroll
    for (int o = 16; o; o >>= 1) v += __shfl_xor_sync(0xffffffffu, v, o);
    if (lane == 0) red[4 + wid] = v;
    __syncthreads();
    const float gsum = red[4] + red[5] + red[6] + red[7];

    const float w = e / gsum;
    wv[tid] = w;
    out[(size_t)(2 + side) * ROWS + (size_t)n * RV_LEN + tid] = w;
    __syncthreads();

    float acc = 0.f;
    #pragma unroll 8
    for (int l = 0; l < RV_LEN; l++) acc += wv[l] * tile[l * TSTRIDE + tid];
    out[(size_t)side * ROWS + (size_t)n * ND + tid] = acc;
}

// ---------------------------------------------------------------------------
extern "C" void kernel_launch(void* const* d_in, const int* in_sizes, int n_in,
                              void* d_out, int out_size)
{
    const float* seq_a  = (const float*)d_in[0];
    const float* seq_b  = (const float*)d_in[1];
    const int*   mask_a = (const int*)d_in[2];
    const int*   mask_b = (const int*)d_in[3];
    const float* W      = (const float*)d_in[4];
    const float* bias   = (const float*)d_in[5];
    float* out = (float*)d_out;

    cudaFuncSetAttribute(gemm_mma_kernel, cudaFuncAttributeMaxDynamicSharedMemorySize, GEMM_SMEM);
    cudaFuncSetAttribute(attn_kernel, cudaFuncAttributeMaxDynamicSharedMemorySize, ATTN_SMEM);

    prep_w_kernel<<<160, 256>>>(W);

    dim3 g1(NREV, 2);
    gemm_mma_kernel<<<g1, 256, GEMM_SMEM>>>(seq_a, seq_b, bias);

    dim3 g2(BZ, 2);
    mean_kernel<<<g2, 1024>>>();

    dim3 g3(NREV, 2);
    attn_kernel<<<g3, 128, ATTN_SMEM>>>(mask_a, mask_b, out);
}

// round 6
// speedup vs baseline: 2.0805x; 1.1189x over previous
#include <cuda_runtime.h>
#include <cuda_bf16.h>
#include <cstdint>

#define RV_NUM 10
#define RV_LEN 128
#define BZ     32
#define NREV   (BZ * RV_NUM)      // 320 reviews
#define ROWS   (NREV * RV_LEN)    // 40960 tokens per tensor
#define KD     300                // in_feat
#define KPAD   320                // padded K (multiple of 32)
#define ND     128                // out_feat / hdim
#define MTOK   (RV_NUM * RV_LEN)  // 1280 tokens per sample

// Scratch (no runtime allocs): transformed features, mean accumulators, split W.
__device__ float g_t[2][ROWS * ND];          // ta / tb (~42 MB, L2-resident)
__device__ float g_mean[2][BZ * ND];         // SUM of transformed feats (atomics)
__device__ __nv_bfloat16 g_wt_hi[ND * KPAD]; // W^T hi  [n][k]
__device__ __nv_bfloat16 g_wt_lo[ND * KPAD]; // W^T lo

// ---------------------------------------------------------------------------
// PTX helpers (sm_103 base target: NO tcgen05; mma.sync / ldmatrix / cp.async)
// ---------------------------------------------------------------------------
__device__ __forceinline__ uint32_t smem_u32(const void* p) {
    uint32_t a;
    asm("{ .reg .u64 t; cvta.to.shared.u64 t, %1; cvt.u32.u64 %0, t; }"
        : "=r"(a) : "l"(p));
    return a;
}
__device__ __forceinline__ void cp_async16(uint32_t dst, const void* src) {
    asm volatile("cp.async.cg.shared.global [%0], [%1], 16;"
                 :: "r"(dst), "l"(src) : "memory");
}
__device__ __forceinline__ void cp_commit() {
    asm volatile("cp.async.commit_group;" ::: "memory");
}
__device__ __forceinline__ void cp_wait0() {
    asm volatile("cp.async.wait_group 0;" ::: "memory");
}
__device__ __forceinline__ void ldmx4(uint32_t addr, uint32_t r[4]) {
    asm volatile("ldmatrix.sync.aligned.m8n8.x4.shared.b16 {%0,%1,%2,%3}, [%4];"
                 : "=r"(r[0]), "=r"(r[1]), "=r"(r[2]), "=r"(r[3]) : "r"(addr));
}
__device__ __forceinline__ void mma16816(float d[4], const uint32_t a[4],
                                         uint32_t b0, uint32_t b1) {
    asm volatile(
        "mma.sync.aligned.m16n8k16.row.col.f32.bf16.bf16.f32 "
        "{%0,%1,%2,%3}, {%4,%5,%6,%7}, {%8,%9}, {%0,%1,%2,%3};"
        : "+f"(d[0]), "+f"(d[1]), "+f"(d[2]), "+f"(d[3])
        : "r"(a[0]), "r"(a[1]), "r"(a[2]), "r"(a[3]), "r"(b0), "r"(b1));
}

// ---------------------------------------------------------------------------
// Kernel 0: split+transpose W -> bf16 hi/lo, and zero the g_mean accumulators.
// ---------------------------------------------------------------------------
__global__ __launch_bounds__(256) void prep_w_kernel(const float* __restrict__ W)
{
    int gid = blockIdx.x * 256 + threadIdx.x;   // 160 * 256 = 40960
    if (gid < 2 * BZ * ND) ((float*)g_mean)[gid] = 0.f;
    int n = gid / KPAD, k = gid % KPAD;
    float v = (k < KD) ? W[k * ND + n] : 0.f;
    __nv_bfloat16 h = __float2bfloat16(v);
    float lo = v - __bfloat162float(h);
    g_wt_hi[gid] = h;
    g_wt_lo[gid] = __float2bfloat16(lo);
}

// ---------------------------------------------------------------------------
// Kernel 1: HMMA GEMM  T = relu(X @ W + b), split-bf16 (hi/lo), fp32 accum.
// Grid (320, 2), 256 threads: 8 warps as 2(m) x 4(n), warp tile 64x32.
// Epilogue additionally column-sum reduces the relu'd tile and atomically
// accumulates into g_mean (fused mean).
// ---------------------------------------------------------------------------
#define BK 32
#define NCHUNK (KPAD / BK)            // 10
#define RS 40                         // bf16 per smem row (80B: conflict-free ldmatrix)
#define AHI_OFF 0
#define ALO_OFF (128 * RS * 2)        // 10240
#define BHI_OFF (2 * 128 * RS * 2)    // 20480
#define BLO_OFF (3 * 128 * RS * 2)    // 30720
#define STAGE_BYTES (4 * 128 * RS * 2)// 40960
#define GEMM_SMEM (2 * STAGE_BYTES)   // 81920

__device__ __forceinline__ void compute_stage(
    uint32_t stgc, int wm, int wn, int lrow, int lk, float acc[4][4][4])
{
    #pragma unroll
    for (int ks = 0; ks < 2; ++ks) {
        uint32_t ah[4][4], al[4][4], bh[4][2], bl[4][2];
        #pragma unroll
        for (int mf = 0; mf < 4; ++mf) {
            uint32_t ad = stgc + AHI_OFF
                        + ((uint32_t)(wm * 64 + mf * 16 + lrow) * RS + ks * 16 + lk) * 2;
            ldmx4(ad, ah[mf]);
            ldmx4(ad + (ALO_OFF - AHI_OFF), al[mf]);
        }
        #pragma unroll
        for (int p = 0; p < 2; ++p) {
            uint32_t bd = stgc + BHI_OFF
                        + ((uint32_t)(wn * 32 + p * 16 + lrow) * RS + ks * 16 + lk) * 2;
            uint32_t r[4];
            ldmx4(bd, r);
            bh[2 * p][0] = r[0]; bh[2 * p + 1][0] = r[1];
            bh[2 * p][1] = r[2]; bh[2 * p + 1][1] = r[3];
            ldmx4(bd + (BLO_OFF - BHI_OFF), r);
            bl[2 * p][0] = r[0]; bl[2 * p + 1][0] = r[1];
            bl[2 * p][1] = r[2]; bl[2 * p + 1][1] = r[3];
        }
        #pragma unroll
        for (int mf = 0; mf < 4; ++mf)
            #pragma unroll
            for (int nf = 0; nf < 4; ++nf) {
                mma16816(acc[mf][nf], ah[mf], bh[nf][0], bh[nf][1]);
                mma16816(acc[mf][nf], al[mf], bh[nf][0], bh[nf][1]);
                mma16816(acc[mf][nf], ah[mf], bl[nf][0], bl[nf][1]);
            }
    }
}

__global__ __launch_bounds__(256) void gemm_mma_kernel(
    const float* __restrict__ A0, const float* __restrict__ A1,
    const float* __restrict__ bias)
{
    extern __shared__ char smem[];
    const uint32_t sb = smem_u32(smem);
    const int tid = threadIdx.x, wid = tid >> 5, lid = tid & 31;
    const int side = blockIdx.y;
    const int rowBase = blockIdx.x * 128;
    const float* __restrict__ A = side ? A1 : A0;

    const int wm = wid >> 2, wn = wid & 3;       // warp grid 2 x 4
    const int g = lid >> 3, lr = lid & 7;
    const int lrow = (g & 1) * 8 + lr;           // ldmatrix row within 16-frag
    const int lk   = (g >> 1) * 8;               // ldmatrix k offset within 16

    float acc[4][4][4];
    #pragma unroll
    for (int i = 0; i < 4; ++i)
        #pragma unroll
        for (int j = 0; j < 4; ++j)
            #pragma unroll
            for (int q = 0; q < 4; ++q) acc[i][j][q] = 0.f;

    // A loader: thread covers row=tid/2, k-half=tid%2 (16 floats = 4 float4)
    const int arow = tid >> 1, ahalf = tid & 1;
    const float* agp = A + (size_t)(rowBase + arow) * KD + ahalf * 16;
    // B loader: thread covers half=tid/128 (hi/lo), n=tid%128, 32 k = 4 x 16B
    const int bhalf = tid >> 7, bn = tid & 127;
    const __nv_bfloat16* bgp = (bhalf ? g_wt_lo : g_wt_hi) + (size_t)bn * KPAD;
    const uint32_t bdst0 = sb + (bhalf ? BLO_OFF : BHI_OFF) + (uint32_t)bn * RS * 2;

    float4 apref[4];

    for (int c = 0; c < NCHUNK; ++c) {
        const int k0 = c * BK;
        const uint32_t stg_off = (uint32_t)(c & 1) * STAGE_BYTES;

        #pragma unroll
        for (int q = 0; q < 4; ++q) {
            int kb = k0 + ahalf * 16 + q * 4;
            apref[q] = (kb < KD) ? *(const float4*)(agp + k0 + q * 4)
                                 : make_float4(0.f, 0.f, 0.f, 0.f);
        }
        #pragma unroll
        for (int q = 0; q < 4; ++q)
            cp_async16(bdst0 + stg_off + q * 16, bgp + k0 + q * 8);
        cp_commit();

        if (c > 0) compute_stage(sb + (uint32_t)((c - 1) & 1) * STAGE_BYTES,
                                 wm, wn, lrow, lk, acc);

        {
            uint32_t off = stg_off + AHI_OFF + ((uint32_t)arow * RS + ahalf * 16) * 2;
            #pragma unroll
            for (int q = 0; q < 4; ++q) {
                float4 v = apref[q];
                __nv_bfloat162 h01 = __floats2bfloat162_rn(v.x, v.y);
                __nv_bfloat162 h23 = __floats2bfloat162_rn(v.z, v.w);
                __nv_bfloat162 l01 = __floats2bfloat162_rn(v.x - __low2float(h01),
                                                           v.y - __high2float(h01));
                __nv_bfloat162 l23 = __floats2bfloat162_rn(v.z - __low2float(h23),
                                                           v.w - __high2float(h23));
                *(uint2*)(smem + off + q * 8) =
                    make_uint2(*(uint32_t*)&h01, *(uint32_t*)&h23);
                *(uint2*)(smem + off + (ALO_OFF - AHI_OFF) + q * 8) =
                    make_uint2(*(uint32_t*)&l01, *(uint32_t*)&l23);
            }
        }
        cp_wait0();
        __syncthreads();
    }
    compute_stage(sb + (uint32_t)((NCHUNK - 1) & 1) * STAGE_BYTES,
                  wm, wn, lrow, lk, acc);

    // Epilogue: bias + ReLU -> global; column sums -> g_mean (fused mean)
    const int trow = lid >> 2, tcol = (lid & 3) * 2;
    float bcol[4][2];
    #pragma unroll
    for (int nf = 0; nf < 4; ++nf) {
        bcol[nf][0] = __ldg(bias + wn * 32 + nf * 8 + tcol);
        bcol[nf][1] = __ldg(bias + wn * 32 + nf * 8 + tcol + 1);
    }
    float cs[4][2];
    #pragma unroll
    for (int nf = 0; nf < 4; ++nf) { cs[nf][0] = 0.f; cs[nf][1] = 0.f; }

    float* Cb = g_t[side];
    #pragma unroll
    for (int mf = 0; mf < 4; ++mf) {
        const int r0 = rowBase + wm * 64 + mf * 16 + trow;
        #pragma unroll
        for (int nf = 0; nf < 4; ++nf) {
            const int c0 = wn * 32 + nf * 8 + tcol;
            float2 v0, v1;
            v0.x = fmaxf(acc[mf][nf][0] + bcol[nf][0], 0.f);
            v0.y = fmaxf(acc[mf][nf][1] + bcol[nf][1], 0.f);
            v1.x = fmaxf(acc[mf][nf][2] + bcol[nf][0], 0.f);
            v1.y = fmaxf(acc[mf][nf][3] + bcol[nf][1], 0.f);
            *(float2*)(Cb + (size_t)r0 * ND + c0)       = v0;
            *(float2*)(Cb + (size_t)(r0 + 8) * ND + c0) = v1;
            cs[nf][0] += v0.x + v1.x;
            cs[nf][1] += v0.y + v1.y;
        }
    }
    // reduce across the 8 trow groups (lanes differing in bits 2..4)
    #pragma unroll
    for (int o = 4; o <= 16; o <<= 1)
        #pragma unroll
        for (int nf = 0; nf < 4; ++nf) {
            cs[nf][0] += __shfl_xor_sync(0xffffffffu, cs[nf][0], o);
            cs[nf][1] += __shfl_xor_sync(0xffffffffu, cs[nf][1], o);
        }
    if (lid < 4) {
        const int b = blockIdx.x / RV_NUM;
        float* mptr = g_mean[side] + b * ND + wn * 32;
        #pragma unroll
        for (int nf = 0; nf < 4; ++nf) {
            atomicAdd(mptr + nf * 8 + tcol,     cs[nf][0]);
            atomicAdd(mptr + nf * 8 + tcol + 1, cs[nf][1]);
        }
    }
}

// ---------------------------------------------------------------------------
// Kernel 2: attention per review — no smem tile; two coalesced float4 passes
// over g_t (L2-resident). Grid (320, 2), 128 threads.
// ---------------------------------------------------------------------------
__global__ __launch_bounds__(128) void attn_kernel(
    const int* __restrict__ mask_a, const int* __restrict__ mask_b,
    float* __restrict__ out)
{
    __shared__ __align__(16) float meanv[128];
    __shared__ __align__(16) float part[4][128];
    __shared__ float sc[128], wv[128], red[8];

    const int side = blockIdx.y;
    const int n    = blockIdx.x;
    const int b    = n / RV_NUM;
    const int tid  = threadIdx.x;
    const int lane = tid & 31, w = tid >> 5;

    const float* __restrict__ T = g_t[side] + (size_t)n * RV_LEN * ND;
    const int*   __restrict__ mask = side ? mask_b : mask_a;

    meanv[tid] = g_mean[side ^ 1][b * ND + tid] * (1.0f / (float)MTOK);
    __syncthreads();

    const float4 mv = *(const float4*)&meanv[lane * 4];

    // Pass 1: scores. Warp w covers tokens [w*32, w*32+32); lanes split the row.
    #pragma unroll 8
    for (int t = 0; t < 32; ++t) {
        const int l = w * 32 + t;
        float4 x = *(const float4*)(T + (size_t)l * ND + lane * 4);
        float p = x.x * mv.x + x.y * mv.y + x.z * mv.z + x.w * mv.w;
        #pragma unroll
        for (int o = 16; o; o >>= 1) p += __shfl_xor_sync(0xffffffffu, p, o);
        if (lane == 0) sc[l] = p;
    }
    __syncthreads();

    // Masked softmax over this review's 128 tokens (thread = token).
    float logit = (mask[n * RV_LEN + tid] > 0) ? sc[tid] : -1e9f;
    float v = logit;
    #pragma unroll
    for (int o = 16; o; o >>= 1) v = fmaxf(v, __shfl_xor_sync(0xffffffffu, v, o));
    if (lane == 0) red[w] = v;
    __syncthreads();
    const float gmax = fmaxf(fmaxf(red[0], red[1]), fmaxf(red[2], red[3]));

    const float e = __expf(logit - gmax);
    v = e;
    #pragma unroll
    for (int o = 16; o; o >>= 1) v += __shfl_xor_sync(0xffffffffu, v, o);
    if (lane == 0) red[4 + w] = v;
    __syncthreads();
    const float gsum = red[4] + red[5] + red[6] + red[7];

    const float wgt = e / gsum;
    wv[tid] = wgt;
    out[(size_t)(2 + side) * ROWS + (size_t)n * RV_LEN + tid] = wgt;
    __syncthreads();

    // Pass 2: weighted sum. Row-group w handles rows l ≡ w (mod 4), lanes split d.
    float4 acc = make_float4(0.f, 0.f, 0.f, 0.f);
    #pragma unroll 8
    for (int l = w; l < RV_LEN; l += 4) {
        float4 x = *(const float4*)(T + (size_t)l * ND + lane * 4);
        const float wl = wv[l];
        acc.x += wl * x.x; acc.y += wl * x.y;
        acc.z += wl * x.z; acc.w += wl * x.w;
    }
    *(float4*)&part[w][lane * 4] = acc;
    __syncthreads();
    float s = part[0][tid] + part[1][tid] + part[2][tid] + part[3][tid];
    out[(size_t)side * ROWS + (size_t)n * ND + tid] = s;
}

// ---------------------------------------------------------------------------
extern "C" void kernel_launch(void* const* d_in, const int* in_sizes, int n_in,
                              void* d_out, int out_size)
{
    const float* seq_a  = (const float*)d_in[0];
    const float* seq_b  = (const float*)d_in[1];
    const int*   mask_a = (const int*)d_in[2];
    const int*   mask_b = (const int*)d_in[3];
    const float* W      = (const float*)d_in[4];
    const float* bias   = (const float*)d_in[5];
    float* out = (float*)d_out;

    cudaFuncSetAttribute(gemm_mma_kernel, cudaFuncAttributeMaxDynamicSharedMemorySize, GEMM_SMEM);

    prep_w_kernel<<<160, 256>>>(W);

    dim3 g1(NREV, 2);
    gemm_mma_kernel<<<g1, 256, GEMM_SMEM>>>(seq_a, seq_b, bias);

    dim3 g3(NREV, 2);
    attn_kernel<<<g3, 128>>>(mask_a, mask_b, out);
}

// round 9
// speedup vs baseline: 2.3791x; 1.1435x over previous
#include <cuda_runtime.h>
#include <cuda_bf16.h>
#include <cstdint>

#define RV_NUM 10
#define RV_LEN 128
#define BZ     32
#define NREV   (BZ * RV_NUM)      // 320 reviews
#define ROWS   (NREV * RV_LEN)    // 40960 tokens per tensor
#define KD     300                // in_feat
#define KPAD   320                // padded K (multiple of 32)
#define ND     128                // out_feat / hdim
#define MTOK   (RV_NUM * RV_LEN)  // 1280 tokens per sample

// Scratch (no runtime allocs): transformed features, mean accumulators, split W.
__device__ float g_t[2][ROWS * ND];          // ta / tb (~42 MB, L2-resident)
__device__ float g_mean[2][BZ * ND];         // SUM of transformed feats (atomics)
__device__ __nv_bfloat16 g_wt_hi[ND * KPAD]; // W^T hi  [n][k]
__device__ __nv_bfloat16 g_wt_lo[ND * KPAD]; // W^T lo

// ---------------------------------------------------------------------------
// PTX helpers (sm_103 base target: NO tcgen05; mma.sync / ldmatrix / cp.async)
// ---------------------------------------------------------------------------
__device__ __forceinline__ uint32_t smem_u32(const void* p) {
    uint32_t a;
    asm("{ .reg .u64 t; cvta.to.shared.u64 t, %1; cvt.u32.u64 %0, t; }"
        : "=r"(a) : "l"(p));
    return a;
}
__device__ __forceinline__ void cp_async16(uint32_t dst, const void* src) {
    asm volatile("cp.async.cg.shared.global [%0], [%1], 16;"
                 :: "r"(dst), "l"(src) : "memory");
}
__device__ __forceinline__ void cp_commit() {
    asm volatile("cp.async.commit_group;" ::: "memory");
}
__device__ __forceinline__ void cp_wait0() {
    asm volatile("cp.async.wait_group 0;" ::: "memory");
}
__device__ __forceinline__ void ldmx4(uint32_t addr, uint32_t r[4]) {
    asm volatile("ldmatrix.sync.aligned.m8n8.x4.shared.b16 {%0,%1,%2,%3}, [%4];"
                 : "=r"(r[0]), "=r"(r[1]), "=r"(r[2]), "=r"(r[3]) : "r"(addr));
}
__device__ __forceinline__ void mma16816(float d[4], const uint32_t a[4],
                                         uint32_t b0, uint32_t b1) {
    asm volatile(
        "mma.sync.aligned.m16n8k16.row.col.f32.bf16.bf16.f32 "
        "{%0,%1,%2,%3}, {%4,%5,%6,%7}, {%8,%9}, {%0,%1,%2,%3};"
        : "+f"(d[0]), "+f"(d[1]), "+f"(d[2]), "+f"(d[3])
        : "r"(a[0]), "r"(a[1]), "r"(a[2]), "r"(a[3]), "r"(b0), "r"(b1));
}

// ---------------------------------------------------------------------------
// Kernel 0: split+transpose W -> bf16 hi/lo, and zero the g_mean accumulators.
// ---------------------------------------------------------------------------
__global__ __launch_bounds__(256) void prep_w_kernel(const float* __restrict__ W)
{
    int gid = blockIdx.x * 256 + threadIdx.x;   // 160 * 256 = 40960
    if (gid < 2 * BZ * ND) ((float*)g_mean)[gid] = 0.f;
    int n = gid / KPAD, k = gid % KPAD;
    float v = (k < KD) ? W[k * ND + n] : 0.f;
    __nv_bfloat16 h = __float2bfloat16(v);
    float lo = v - __bfloat162float(h);
    g_wt_hi[gid] = h;
    g_wt_lo[gid] = __float2bfloat16(lo);
}

// ---------------------------------------------------------------------------
// Kernel 1: HMMA GEMM  T = relu(X @ W + b), split-bf16 (hi/lo), fp32 accum.
// Grid (320, 2), 256 threads: 8 warps as 2(m) x 4(n), warp tile 64x32.
// __launch_bounds__(256,2): cap regs at 128 -> 2 CTAs/SM (16 warps/SM).
// Epilogue: bias+ReLU store + fused column-sum into g_mean via atomics.
// ---------------------------------------------------------------------------
#define BK 32
#define NCHUNK (KPAD / BK)            // 10
#define RS 40                         // bf16/row (80B rows: LDSM conflict-free)
#define AHI_OFF 0
#define ALO_OFF (128 * RS * 2)        // 10240
#define BHI_OFF (2 * 128 * RS * 2)    // 20480
#define BLO_OFF (3 * 128 * RS * 2)    // 30720
#define STAGE_BYTES (4 * 128 * RS * 2)// 40960
#define GEMM_SMEM (2 * STAGE_BYTES)   // 81920

// Restructured for low live-register count: B fragments loaded per-p and
// consumed immediately (8 live B regs), A frags loaded once per ks (32 regs).
__device__ __forceinline__ void compute_stage(
    uint32_t stgc, int wm, int wn, int lrow, int lk, float acc[4][4][4])
{
    #pragma unroll
    for (int ks = 0; ks < 2; ++ks) {
        uint32_t ah[4][4], al[4][4];
        #pragma unroll
        for (int mf = 0; mf < 4; ++mf) {
            uint32_t ad = stgc + AHI_OFF
                        + ((uint32_t)(wm * 64 + mf * 16 + lrow) * RS + ks * 16 + lk) * 2;
            ldmx4(ad, ah[mf]);
            ldmx4(ad + (ALO_OFF - AHI_OFF), al[mf]);
        }
        #pragma unroll
        for (int p = 0; p < 2; ++p) {
            uint32_t bd = stgc + BHI_OFF
                        + ((uint32_t)(wn * 32 + p * 16 + lrow) * RS + ks * 16 + lk) * 2;
            uint32_t rh[4], rl[4];
            ldmx4(bd, rh);
            ldmx4(bd + (BLO_OFF - BHI_OFF), rl);
            #pragma unroll
            for (int j = 0; j < 2; ++j) {
                const int nf = 2 * p + j;
                #pragma unroll
                for (int mf = 0; mf < 4; ++mf) {
                    mma16816(acc[mf][nf], ah[mf], rh[j], rh[j + 2]);
                    mma16816(acc[mf][nf], al[mf], rh[j], rh[j + 2]);
                    mma16816(acc[mf][nf], ah[mf], rl[j], rl[j + 2]);
                }
            }
        }
    }
}

__global__ __launch_bounds__(256, 2) void gemm_mma_kernel(
    const float* __restrict__ A0, const float* __restrict__ A1,
    const float* __restrict__ bias)
{
    extern __shared__ char smem[];
    const uint32_t sb = smem_u32(smem);
    const int tid = threadIdx.x, wid = tid >> 5, lid = tid & 31;
    const int side = blockIdx.y;
    const int rowBase = blockIdx.x * 128;
    const float* __restrict__ A = side ? A1 : A0;

    const int wm = wid >> 2, wn = wid & 3;       // warp grid 2 x 4
    const int g = lid >> 3, lr = lid & 7;
    const int lrow = (g & 1) * 8 + lr;           // ldmatrix row within 16-frag
    const int lk   = (g >> 1) * 8;               // ldmatrix k offset within 16

    float acc[4][4][4];
    #pragma unroll
    for (int i = 0; i < 4; ++i)
        #pragma unroll
        for (int j = 0; j < 4; ++j)
            #pragma unroll
            for (int q = 0; q < 4; ++q) acc[i][j][q] = 0.f;

    // A loader: thread covers row=tid/2, k-half=tid%2 (16 floats = 4 float4)
    const int arow = tid >> 1, ahalf = tid & 1;
    const float* agp = A + (size_t)(rowBase + arow) * KD + ahalf * 16;
    // B loader: thread covers half=tid/128 (hi/lo), n=tid%128, 32 k = 4 x 16B
    const int bhalf = tid >> 7, bn = tid & 127;
    const __nv_bfloat16* bgp = (bhalf ? g_wt_lo : g_wt_hi) + (size_t)bn * KPAD;
    const uint32_t bdst0 = sb + (bhalf ? BLO_OFF : BHI_OFF) + (uint32_t)bn * RS * 2;

    float4 apref[4];

    for (int c = 0; c < NCHUNK; ++c) {
        const int k0 = c * BK;
        const uint32_t stg_off = (uint32_t)(c & 1) * STAGE_BYTES;

        #pragma unroll
        for (int q = 0; q < 4; ++q) {
            int kb = k0 + ahalf * 16 + q * 4;
            apref[q] = (kb < KD) ? *(const float4*)(agp + k0 + q * 4)
                                 : make_float4(0.f, 0.f, 0.f, 0.f);
        }
        #pragma unroll
        for (int q = 0; q < 4; ++q)
            cp_async16(bdst0 + stg_off + q * 16, bgp + k0 + q * 8);
        cp_commit();

        if (c > 0) compute_stage(sb + (uint32_t)((c - 1) & 1) * STAGE_BYTES,
                                 wm, wn, lrow, lk, acc);

        {
            uint32_t off = stg_off + AHI_OFF + ((uint32_t)arow * RS + ahalf * 16) * 2;
            #pragma unroll
            for (int q = 0; q < 4; ++q) {
                float4 v = apref[q];
                __nv_bfloat162 h01 = __floats2bfloat162_rn(v.x, v.y);
                __nv_bfloat162 h23 = __floats2bfloat162_rn(v.z, v.w);
                __nv_bfloat162 l01 = __floats2bfloat162_rn(v.x - __low2float(h01),
                                                           v.y - __high2float(h01));
                __nv_bfloat162 l23 = __floats2bfloat162_rn(v.z - __low2float(h23),
                                                           v.w - __high2float(h23));
                *(uint2*)(smem + off + q * 8) =
                    make_uint2(*(uint32_t*)&h01, *(uint32_t*)&h23);
                *(uint2*)(smem + off + (ALO_OFF - AHI_OFF) + q * 8) =
                    make_uint2(*(uint32_t*)&l01, *(uint32_t*)&l23);
            }
        }
        cp_wait0();
        __syncthreads();
    }
    compute_stage(sb + (uint32_t)((NCHUNK - 1) & 1) * STAGE_BYTES,
                  wm, wn, lrow, lk, acc);

    // Epilogue: bias + ReLU -> global; column sums -> g_mean (fused mean)
    const int trow = lid >> 2, tcol = (lid & 3) * 2;
    float bcol[4][2];
    #pragma unroll
    for (int nf = 0; nf < 4; ++nf) {
        bcol[nf][0] = __ldg(bias + wn * 32 + nf * 8 + tcol);
        bcol[nf][1] = __ldg(bias + wn * 32 + nf * 8 + tcol + 1);
    }
    float cs[4][2];
    #pragma unroll
    for (int nf = 0; nf < 4; ++nf) { cs[nf][0] = 0.f; cs[nf][1] = 0.f; }

    float* Cb = g_t[side];
    #pragma unroll
    for (int mf = 0; mf < 4; ++mf) {
        const int r0 = rowBase + wm * 64 + mf * 16 + trow;
        #pragma unroll
        for (int nf = 0; nf < 4; ++nf) {
            const int c0 = wn * 32 + nf * 8 + tcol;
            float2 v0, v1;
            v0.x = fmaxf(acc[mf][nf][0] + bcol[nf][0], 0.f);
            v0.y = fmaxf(acc[mf][nf][1] + bcol[nf][1], 0.f);
            v1.x = fmaxf(acc[mf][nf][2] + bcol[nf][0], 0.f);
            v1.y = fmaxf(acc[mf][nf][3] + bcol[nf][1], 0.f);
            *(float2*)(Cb + (size_t)r0 * ND + c0)       = v0;
            *(float2*)(Cb + (size_t)(r0 + 8) * ND + c0) = v1;
            cs[nf][0] += v0.x + v1.x;
            cs[nf][1] += v0.y + v1.y;
        }
    }
    #pragma unroll
    for (int o = 4; o <= 16; o <<= 1)
        #pragma unroll
        for (int nf = 0; nf < 4; ++nf) {
            cs[nf][0] += __shfl_xor_sync(0xffffffffu, cs[nf][0], o);
            cs[nf][1] += __shfl_xor_sync(0xffffffffu, cs[nf][1], o);
        }
    if (lid < 4) {
        const int b = blockIdx.x / RV_NUM;
        float* mptr = g_mean[side] + b * ND + wn * 32;
        #pragma unroll
        for (int nf = 0; nf < 4; ++nf) {
            atomicAdd(mptr + nf * 8 + tcol,     cs[nf][0]);
            atomicAdd(mptr + nf * 8 + tcol + 1, cs[nf][1]);
        }
    }
}

// ---------------------------------------------------------------------------
// Kernel 2: attention per review — two coalesced float4 passes over g_t.
// Grid (320, 2), 128 threads.
// ---------------------------------------------------------------------------
__global__ __launch_bounds__(128) void attn_kernel(
    const int* __restrict__ mask_a, const int* __restrict__ mask_b,
    float* __restrict__ out)
{
    __shared__ __align__(16) float meanv[128];
    __shared__ __align__(16) float part[4][128];
    __shared__ float sc[128], wv[128], red[8];

    const int side = blockIdx.y;
    const int n    = blockIdx.x;
    const int b    = n / RV_NUM;
    const int tid  = threadIdx.x;
    const int lane = tid & 31, w = tid >> 5;

    const float* __restrict__ T = g_t[side] + (size_t)n * RV_LEN * ND;
    const int*   __restrict__ mask = side ? mask_b : mask_a;

    meanv[tid] = g_mean[side ^ 1][b * ND + tid] * (1.0f / (float)MTOK);
    __syncthreads();

    const float4 mv = *(const float4*)&meanv[lane * 4];

    // Pass 1: scores. Warp w covers tokens [w*32, w*32+32); lanes split the row.
    #pragma unroll 8
    for (int t = 0; t < 32; ++t) {
        const int l = w * 32 + t;
        float4 x = *(const float4*)(T + (size_t)l * ND + lane * 4);
        float p = x.x * mv.x + x.y * mv.y + x.z * mv.z + x.w * mv.w;
        #pragma unroll
        for (int o = 16; o; o >>= 1) p += __shfl_xor_sync(0xffffffffu, p, o);
        if (lane == 0) sc[l] = p;
    }
    __syncthreads();

    // Masked softmax over this review's 128 tokens (thread = token).
    float logit = (mask[n * RV_LEN + tid] > 0) ? sc[tid] : -1e9f;
    float v = logit;
    #pragma unroll
    for (int o = 16; o; o >>= 1) v = fmaxf(v, __shfl_xor_sync(0xffffffffu, v, o));
    if (lane == 0) red[w] = v;
    __syncthreads();
    const float gmax = fmaxf(fmaxf(red[0], red[1]), fmaxf(red[2], red[3]));

    const float e = __expf(logit - gmax);
    v = e;
    #pragma unroll
    for (int o = 16; o; o >>= 1) v += __shfl_xor_sync(0xffffffffu, v, o);
    if (lane == 0) red[4 + w] = v;
    __syncthreads();
    const float gsum = red[4] + red[5] + red[6] + red[7];

    const float wgt = e / gsum;
    wv[tid] = wgt;
    out[(size_t)(2 + side) * ROWS + (size_t)n * RV_LEN + tid] = wgt;
    __syncthreads();

    // Pass 2: weighted sum. Row-group w handles rows l ≡ w (mod 4), lanes split d.
    float4 acc = make_float4(0.f, 0.f, 0.f, 0.f);
    #pragma unroll 8
    for (int l = w; l < RV_LEN; l += 4) {
        float4 x = *(const float4*)(T + (size_t)l * ND + lane * 4);
        const float wl = wv[l];
        acc.x += wl * x.x; acc.y += wl * x.y;
        acc.z += wl * x.z; acc.w += wl * x.w;
    }
    *(float4*)&part[w][lane * 4] = acc;
    __syncthreads();
    float s = part[0][tid] + part[1][tid] + part[2][tid] + part[3][tid];
    out[(size_t)side * ROWS + (size_t)n * ND + tid] = s;
}

// ---------------------------------------------------------------------------
extern "C" void kernel_launch(void* const* d_in, const int* in_sizes, int n_in,
                              void* d_out, int out_size)
{
    const float* seq_a  = (const float*)d_in[0];
    const float* seq_b  = (const float*)d_in[1];
    const int*   mask_a = (const int*)d_in[2];
    const int*   mask_b = (const int*)d_in[3];
    const float* W      = (const float*)d_in[4];
    const float* bias   = (const float*)d_in[5];
    float* out = (float*)d_out;

    cudaFuncSetAttribute(gemm_mma_kernel, cudaFuncAttributeMaxDynamicSharedMemorySize, GEMM_SMEM);

    prep_w_kernel<<<160, 256>>>(W);

    dim3 g1(NREV, 2);
    gemm_mma_kernel<<<g1, 256, GEMM_SMEM>>>(seq_a, seq_b, bias);

    dim3 g3(NREV, 2);
    attn_kernel<<<g3, 128>>>(mask_a, mask_b, out);
}

// round 10
// speedup vs baseline: 3.0511x; 1.2825x over previous
#include <cuda_runtime.h>
#include <cuda_fp16.h>
#include <cstdint>

#define RV_NUM 10
#define RV_LEN 128
#define BZ     32
#define NREV   (BZ * RV_NUM)      // 320 reviews
#define ROWS   (NREV * RV_LEN)    // 40960 tokens per tensor
#define KD     300                // in_feat
#define KPAD   320                // padded K (multiple of 32)
#define ND     128                // out_feat / hdim
#define MTOK   (RV_NUM * RV_LEN)  // 1280 tokens per sample

// Scratch (no runtime allocs): transformed features, mean accumulators, W fp16.
__device__ float g_t[2][ROWS * ND];       // ta / tb (~42 MB, L2-resident)
__device__ float g_mean[2][BZ * ND];      // SUM of transformed feats (atomics)
__device__ __half g_wt_hi[ND * KPAD];     // W^T rounded to fp16  [n][k]

// ---------------------------------------------------------------------------
// PTX helpers (sm_103 base target: NO tcgen05; mma.sync / ldmatrix / cp.async)
// ---------------------------------------------------------------------------
__device__ __forceinline__ uint32_t smem_u32(const void* p) {
    uint32_t a;
    asm("{ .reg .u64 t; cvta.to.shared.u64 t, %1; cvt.u32.u64 %0, t; }"
        : "=r"(a) : "l"(p));
    return a;
}
__device__ __forceinline__ void cp_async16(uint32_t dst, const void* src) {
    asm volatile("cp.async.cg.shared.global [%0], [%1], 16;"
                 :: "r"(dst), "l"(src) : "memory");
}
__device__ __forceinline__ void cp_commit() {
    asm volatile("cp.async.commit_group;" ::: "memory");
}
__device__ __forceinline__ void cp_wait0() {
    asm volatile("cp.async.wait_group 0;" ::: "memory");
}
__device__ __forceinline__ void ldmx4(uint32_t addr, uint32_t r[4]) {
    asm volatile("ldmatrix.sync.aligned.m8n8.x4.shared.b16 {%0,%1,%2,%3}, [%4];"
                 : "=r"(r[0]), "=r"(r[1]), "=r"(r[2]), "=r"(r[3]) : "r"(addr));
}
__device__ __forceinline__ void mma16816(float d[4], const uint32_t a[4],
                                         uint32_t b0, uint32_t b1) {
    asm volatile(
        "mma.sync.aligned.m16n8k16.row.col.f32.f16.f16.f32 "
        "{%0,%1,%2,%3}, {%4,%5,%6,%7}, {%8,%9}, {%0,%1,%2,%3};"
        : "+f"(d[0]), "+f"(d[1]), "+f"(d[2]), "+f"(d[3])
        : "r"(a[0]), "r"(a[1]), "r"(a[2]), "r"(a[3]), "r"(b0), "r"(b1));
}

// ---------------------------------------------------------------------------
// Kernel 0: transpose W [300,128] f32 -> fp16 [128,320]; zero g_mean.
// ---------------------------------------------------------------------------
__global__ __launch_bounds__(256) void prep_w_kernel(const float* __restrict__ W)
{
    int gid = blockIdx.x * 256 + threadIdx.x;   // 160 * 256 = 40960
    if (gid < 2 * BZ * ND) ((float*)g_mean)[gid] = 0.f;
    int n = gid / KPAD, k = gid % KPAD;
    float v = (k < KD) ? W[k * ND + n] : 0.f;
    g_wt_hi[gid] = __float2half_rn(v);
}

// ---------------------------------------------------------------------------
// Kernel 1: HMMA GEMM  T = relu(X @ W + b), fp16 2-pass (A split hi/lo, W fp16),
// fp32 accum. Grid (320, 2), 256 threads: 8 warps as 2(m) x 4(n), 64x32 each.
// __launch_bounds__(256,2): 2 CTAs/SM. Epilogue: bias+ReLU + fused mean atomics.
// ---------------------------------------------------------------------------
#define BK 32
#define NCHUNK (KPAD / BK)            // 10
#define RS 40                         // fp16/row (80B rows: LDSM conflict-free)
#define AHI_OFF 0
#define ALO_OFF (128 * RS * 2)        // 10240
#define BHI_OFF (2 * 128 * RS * 2)    // 20480
#define STAGE_BYTES (3 * 128 * RS * 2)// 30720
#define GEMM_SMEM (2 * STAGE_BYTES)   // 61440

// Pass-major ordering: same accumulator revisited at distance 4 (breaks the
// acc RAW chain); B fragment regs reused across all 8 mf-mmas of a (p).
__device__ __forceinline__ void compute_stage(
    uint32_t stgc, int wm, int wn, int lrow, int lk, float acc[4][4][4])
{
    #pragma unroll
    for (int ks = 0; ks < 2; ++ks) {
        uint32_t ah[4][4], al[4][4];
        #pragma unroll
        for (int mf = 0; mf < 4; ++mf) {
            uint32_t ad = stgc + AHI_OFF
                        + ((uint32_t)(wm * 64 + mf * 16 + lrow) * RS + ks * 16 + lk) * 2;
            ldmx4(ad, ah[mf]);
            ldmx4(ad + (ALO_OFF - AHI_OFF), al[mf]);
        }
        #pragma unroll
        for (int p = 0; p < 2; ++p) {
            uint32_t bd = stgc + BHI_OFF
                        + ((uint32_t)(wn * 32 + p * 16 + lrow) * RS + ks * 16 + lk) * 2;
            uint32_t rh[4];
            ldmx4(bd, rh);
            #pragma unroll
            for (int j = 0; j < 2; ++j) {
                const int nf = 2 * p + j;
                #pragma unroll
                for (int mf = 0; mf < 4; ++mf)
                    mma16816(acc[mf][nf], ah[mf], rh[j], rh[j + 2]);
                #pragma unroll
                for (int mf = 0; mf < 4; ++mf)
                    mma16816(acc[mf][nf], al[mf], rh[j], rh[j + 2]);
            }
        }
    }
}

__global__ __launch_bounds__(256, 2) void gemm_mma_kernel(
    const float* __restrict__ A0, const float* __restrict__ A1,
    const float* __restrict__ bias)
{
    extern __shared__ char smem[];
    const uint32_t sb = smem_u32(smem);
    const int tid = threadIdx.x, wid = tid >> 5, lid = tid & 31;
    const int side = blockIdx.y;
    const int rowBase = blockIdx.x * 128;
    const float* __restrict__ A = side ? A1 : A0;

    const int wm = wid >> 2, wn = wid & 3;       // warp grid 2 x 4
    const int g = lid >> 3, lr = lid & 7;
    const int lrow = (g & 1) * 8 + lr;           // ldmatrix row within 16-frag
    const int lk   = (g >> 1) * 8;               // ldmatrix k offset within 16

    float acc[4][4][4];
    #pragma unroll
    for (int i = 0; i < 4; ++i)
        #pragma unroll
        for (int j = 0; j < 4; ++j)
            #pragma unroll
            for (int q = 0; q < 4; ++q) acc[i][j][q] = 0.f;

    // A loader: thread covers row=tid/2, k-half=tid%2 (16 floats = 4 float4)
    const int arow = tid >> 1, ahalf = tid & 1;
    const float* agp = A + (size_t)(rowBase + arow) * KD + ahalf * 16;
    // B loader: thread covers row=tid/2, k-quarter=tid%2 (16 halfs = 2 x 16B)
    const int bn = tid >> 1, bq = tid & 1;
    const __half* bgp = g_wt_hi + (size_t)bn * KPAD + bq * 16;
    const uint32_t bdst0 = sb + BHI_OFF + (uint32_t)bn * RS * 2 + bq * 32;

    float4 apref[4];

    for (int c = 0; c < NCHUNK; ++c) {
        const int k0 = c * BK;
        const uint32_t stg_off = (uint32_t)(c & 1) * STAGE_BYTES;

        #pragma unroll
        for (int q = 0; q < 4; ++q) {
            int kb = k0 + ahalf * 16 + q * 4;
            apref[q] = (kb < KD) ? *(const float4*)(agp + k0 + q * 4)
                                 : make_float4(0.f, 0.f, 0.f, 0.f);
        }
        cp_async16(bdst0 + stg_off,      bgp + k0);
        cp_async16(bdst0 + stg_off + 16, bgp + k0 + 8);
        cp_commit();

        if (c > 0) compute_stage(sb + (uint32_t)((c - 1) & 1) * STAGE_BYTES,
                                 wm, wn, lrow, lk, acc);

        {
            uint32_t off = stg_off + AHI_OFF + ((uint32_t)arow * RS + ahalf * 16) * 2;
            #pragma unroll
            for (int q = 0; q < 4; ++q) {
                float4 v = apref[q];
                __half2 h01 = __floats2half2_rn(v.x, v.y);
                __half2 h23 = __floats2half2_rn(v.z, v.w);
                __half2 l01 = __floats2half2_rn(v.x - __low2float(h01),
                                                v.y - __high2float(h01));
                __half2 l23 = __floats2half2_rn(v.z - __low2float(h23),
                                                v.w - __high2float(h23));
                *(uint2*)(smem + off + q * 8) =
                    make_uint2(*(uint32_t*)&h01, *(uint32_t*)&h23);
                *(uint2*)(smem + off + (ALO_OFF - AHI_OFF) + q * 8) =
                    make_uint2(*(uint32_t*)&l01, *(uint32_t*)&l23);
            }
        }
        cp_wait0();
        __syncthreads();
    }
    compute_stage(sb + (uint32_t)((NCHUNK - 1) & 1) * STAGE_BYTES,
                  wm, wn, lrow, lk, acc);

    // Epilogue: bias + ReLU -> global; column sums -> g_mean (fused mean)
    const int trow = lid >> 2, tcol = (lid & 3) * 2;
    float bcol[4][2];
    #pragma unroll
    for (int nf = 0; nf < 4; ++nf) {
        bcol[nf][0] = __ldg(bias + wn * 32 + nf * 8 + tcol);
        bcol[nf][1] = __ldg(bias + wn * 32 + nf * 8 + tcol + 1);
    }
    float cs[4][2];
    #pragma unroll
    for (int nf = 0; nf < 4; ++nf) { cs[nf][0] = 0.f; cs[nf][1] = 0.f; }

    float* Cb = g_t[side];
    #pragma unroll
    for (int mf = 0; mf < 4; ++mf) {
        const int r0 = rowBase + wm * 64 + mf * 16 + trow;
        #pragma unroll
        for (int nf = 0; nf < 4; ++nf) {
            const int c0 = wn * 32 + nf * 8 + tcol;
            float2 v0, v1;
            v0.x = fmaxf(acc[mf][nf][0] + bcol[nf][0], 0.f);
            v0.y = fmaxf(acc[mf][nf][1] + bcol[nf][1], 0.f);
            v1.x = fmaxf(acc[mf][nf][2] + bcol[nf][0], 0.f);
            v1.y = fmaxf(acc[mf][nf][3] + bcol[nf][1], 0.f);
            *(float2*)(Cb + (size_t)r0 * ND + c0)       = v0;
            *(float2*)(Cb + (size_t)(r0 + 8) * ND + c0) = v1;
            cs[nf][0] += v0.x + v1.x;
            cs[nf][1] += v0.y + v1.y;
        }
    }
    #pragma unroll
    for (int o = 4; o <= 16; o <<= 1)
        #pragma unroll
        for (int nf = 0; nf < 4; ++nf) {
            cs[nf][0] += __shfl_xor_sync(0xffffffffu, cs[nf][0], o);
            cs[nf][1] += __shfl_xor_sync(0xffffffffu, cs[nf][1], o);
        }
    if (lid < 4) {
        const int b = blockIdx.x / RV_NUM;
        float* mptr = g_mean[side] + b * ND + wn * 32;
        #pragma unroll
        for (int nf = 0; nf < 4; ++nf) {
            atomicAdd(mptr + nf * 8 + tcol,     cs[nf][0]);
            atomicAdd(mptr + nf * 8 + tcol + 1, cs[nf][1]);
        }
    }
}

// ---------------------------------------------------------------------------
// Kernel 2: attention per review — two coalesced float4 passes over g_t.
// Grid (320, 2), 128 threads.
// ---------------------------------------------------------------------------
__global__ __launch_bounds__(128) void attn_kernel(
    const int* __restrict__ mask_a, const int* __restrict__ mask_b,
    float* __restrict__ out)
{
    __shared__ __align__(16) float meanv[128];
    __shared__ __align__(16) float part[4][128];
    __shared__ float sc[128], wv[128], red[8];

    const int side = blockIdx.y;
    const int n    = blockIdx.x;
    const int b    = n / RV_NUM;
    const int tid  = threadIdx.x;
    const int lane = tid & 31, w = tid >> 5;

    const float* __restrict__ T = g_t[side] + (size_t)n * RV_LEN * ND;
    const int*   __restrict__ mask = side ? mask_b : mask_a;

    meanv[tid] = g_mean[side ^ 1][b * ND + tid] * (1.0f / (float)MTOK);
    __syncthreads();

    const float4 mv = *(const float4*)&meanv[lane * 4];

    // Pass 1: scores. Warp w covers tokens [w*32, w*32+32); lanes split the row.
    #pragma unroll 8
    for (int t = 0; t < 32; ++t) {
        const int l = w * 32 + t;
        float4 x = *(const float4*)(T + (size_t)l * ND + lane * 4);
        float p = x.x * mv.x + x.y * mv.y + x.z * mv.z + x.w * mv.w;
        #pragma unroll
        for (int o = 16; o; o >>= 1) p += __shfl_xor_sync(0xffffffffu, p, o);
        if (lane == 0) sc[l] = p;
    }
    __syncthreads();

    // Masked softmax over this review's 128 tokens (thread = token).
    float logit = (mask[n * RV_LEN + tid] > 0) ? sc[tid] : -1e9f;
    float v = logit;
    #pragma unroll
    for (int o = 16; o; o >>= 1) v = fmaxf(v, __shfl_xor_sync(0xffffffffu, v, o));
    if (lane == 0) red[w] = v;
    __syncthreads();
    const float gmax = fmaxf(fmaxf(red[0], red[1]), fmaxf(red[2], red[3]));

    const float e = __expf(logit - gmax);
    v = e;
    #pragma unroll
    for (int o = 16; o; o >>= 1) v += __shfl_xor_sync(0xffffffffu, v, o);
    if (lane == 0) red[4 + w] = v;
    __syncthreads();
    const float gsum = red[4] + red[5] + red[6] + red[7];

    const float wgt = e / gsum;
    wv[tid] = wgt;
    out[(size_t)(2 + side) * ROWS + (size_t)n * RV_LEN + tid] = wgt;
    __syncthreads();

    // Pass 2: weighted sum. Row-group w handles rows l ≡ w (mod 4), lanes split d.
    float4 acc = make_float4(0.f, 0.f, 0.f, 0.f);
    #pragma unroll 8
    for (int l = w; l < RV_LEN; l += 4) {
        float4 x = *(const float4*)(T + (size_t)l * ND + lane * 4);
        const float wl = wv[l];
        acc.x += wl * x.x; acc.y += wl * x.y;
        acc.z += wl * x.z; acc.w += wl * x.w;
    }
    *(float4*)&part[w][lane * 4] = acc;
    __syncthreads();
    float s = part[0][tid] + part[1][tid] + part[2][tid] + part[3][tid];
    out[(size_t)side * ROWS + (size_t)n * ND + tid] = s;
}

// ---------------------------------------------------------------------------
extern "C" void kernel_launch(void* const* d_in, const int* in_sizes, int n_in,
                              void* d_out, int out_size)
{
    const float* seq_a  = (const float*)d_in[0];
    const float* seq_b  = (const float*)d_in[1];
    const int*   mask_a = (const int*)d_in[2];
    const int*   mask_b = (const int*)d_in[3];
    const float* W      = (const float*)d_in[4];
    const float* bias   = (const float*)d_in[5];
    float* out = (float*)d_out;

    cudaFuncSetAttribute(gemm_mma_kernel, cudaFuncAttributeMaxDynamicSharedMemorySize, GEMM_SMEM);

    prep_w_kernel<<<160, 256>>>(W);

    dim3 g1(NREV, 2);
    gemm_mma_kernel<<<g1, 256, GEMM_SMEM>>>(seq_a, seq_b, bias);

    dim3 g3(NREV, 2);
    attn_kernel<<<g3, 128>>>(mask_a, mask_b, out);
}

// round 11
// speedup vs baseline: 3.5063x; 1.1492x over previous
#include <cuda_runtime.h>
#include <cuda_fp16.h>
#include <cstdint>

#define RV_NUM 10
#define RV_LEN 128
#define BZ     32
#define NREV   (BZ * RV_NUM)      // 320 reviews
#define ROWS   (NREV * RV_LEN)    // 40960 tokens per tensor
#define KD     300                // in_feat
#define KPAD   320                // padded K (multiple of 32)
#define ND     128                // out_feat / hdim
#define MTOK   (RV_NUM * RV_LEN)  // 1280 tokens per sample

// Scratch (no runtime allocs): transformed features, mean accumulators, W fp16.
__device__ float g_t[2][ROWS * ND];       // ta / tb (~42 MB, L2-resident)
__device__ float g_mean[2][BZ * ND];      // SUM of transformed feats (atomics)
__device__ __half g_wt_hi[ND * KPAD];     // W^T rounded to fp16  [n][k]

// ---------------------------------------------------------------------------
// PTX helpers (sm_103 base target: NO tcgen05; mma.sync / ldmatrix / cp.async)
// ---------------------------------------------------------------------------
__device__ __forceinline__ uint32_t smem_u32(const void* p) {
    uint32_t a;
    asm("{ .reg .u64 t; cvta.to.shared.u64 t, %1; cvt.u32.u64 %0, t; }"
        : "=r"(a) : "l"(p));
    return a;
}
__device__ __forceinline__ void cp_async16(uint32_t dst, const void* src) {
    asm volatile("cp.async.cg.shared.global [%0], [%1], 16;"
                 :: "r"(dst), "l"(src) : "memory");
}
__device__ __forceinline__ void cp_commit() {
    asm volatile("cp.async.commit_group;" ::: "memory");
}
__device__ __forceinline__ void cp_wait0() {
    asm volatile("cp.async.wait_group 0;" ::: "memory");
}
__device__ __forceinline__ void ldmx4(uint32_t addr, uint32_t r[4]) {
    asm volatile("ldmatrix.sync.aligned.m8n8.x4.shared.b16 {%0,%1,%2,%3}, [%4];"
                 : "=r"(r[0]), "=r"(r[1]), "=r"(r[2]), "=r"(r[3]) : "r"(addr));
}
__device__ __forceinline__ void mma16816(float d[4], const uint32_t a[4],
                                         uint32_t b0, uint32_t b1) {
    asm volatile(
        "mma.sync.aligned.m16n8k16.row.col.f32.f16.f16.f32 "
        "{%0,%1,%2,%3}, {%4,%5,%6,%7}, {%8,%9}, {%0,%1,%2,%3};"
        : "+f"(d[0]), "+f"(d[1]), "+f"(d[2]), "+f"(d[3])
        : "r"(a[0]), "r"(a[1]), "r"(a[2]), "r"(a[3]), "r"(b0), "r"(b1));
}

// ---------------------------------------------------------------------------
// Kernel 0: transpose W [300,128] f32 -> fp16 [128,320]; zero g_mean.
// ---------------------------------------------------------------------------
__global__ __launch_bounds__(256) void prep_w_kernel(const float* __restrict__ W)
{
    int gid = blockIdx.x * 256 + threadIdx.x;   // 160 * 256 = 40960
    if (gid < 2 * BZ * ND) ((float*)g_mean)[gid] = 0.f;
    int n = gid / KPAD, k = gid % KPAD;
    float v = (k < KD) ? W[k * ND + n] : 0.f;
    g_wt_hi[gid] = __float2half_rn(v);
}

// ---------------------------------------------------------------------------
// Kernel 1: HMMA GEMM  T = relu(X @ W + b), fp16 2-pass (A split hi/lo), fp32
// accum. M-tile 64 (occupancy experiment): grid (640, 2), 256 threads,
// 8 warps as 2(m) x 4(n), warp tile 32x32, __launch_bounds__(256,3):
// 3 CTAs/SM = 24 warps/SM. Epilogue: bias+ReLU + fused mean atomics.
// ---------------------------------------------------------------------------
#define BM 64
#define BK 32
#define NCHUNK (KPAD / BK)            // 10
#define RS 40                         // fp16/row (80B rows: LDSM conflict-free)
#define AHI_OFF 0
#define ALO_OFF (BM * RS * 2)         // 5120
#define BHI_OFF (2 * BM * RS * 2)     // 10240
#define STAGE_BYTES (BHI_OFF + 128 * RS * 2)  // 20480
#define GEMM_SMEM (2 * STAGE_BYTES)   // 40960

// Per (p): 4 hi-MMAs then 4 lo-MMAs -> same-accumulator reuse distance 4.
__device__ __forceinline__ void compute_stage(
    uint32_t stgc, int wm, int wn, int lrow, int lk, float acc[2][4][4])
{
    #pragma unroll
    for (int ks = 0; ks < 2; ++ks) {
        uint32_t ah[2][4], al[2][4];
        #pragma unroll
        for (int mf = 0; mf < 2; ++mf) {
            uint32_t ad = stgc + AHI_OFF
                        + ((uint32_t)(wm * 32 + mf * 16 + lrow) * RS + ks * 16 + lk) * 2;
            ldmx4(ad, ah[mf]);
            ldmx4(ad + (ALO_OFF - AHI_OFF), al[mf]);
        }
        #pragma unroll
        for (int p = 0; p < 2; ++p) {
            uint32_t bd = stgc + BHI_OFF
                        + ((uint32_t)(wn * 32 + p * 16 + lrow) * RS + ks * 16 + lk) * 2;
            uint32_t rh[4];
            ldmx4(bd, rh);
            #pragma unroll
            for (int j = 0; j < 2; ++j)
                #pragma unroll
                for (int mf = 0; mf < 2; ++mf)
                    mma16816(acc[mf][2 * p + j], ah[mf], rh[j], rh[j + 2]);
            #pragma unroll
            for (int j = 0; j < 2; ++j)
                #pragma unroll
                for (int mf = 0; mf < 2; ++mf)
                    mma16816(acc[mf][2 * p + j], al[mf], rh[j], rh[j + 2]);
        }
    }
}

__global__ __launch_bounds__(256, 3) void gemm_mma_kernel(
    const float* __restrict__ A0, const float* __restrict__ A1,
    const float* __restrict__ bias)
{
    extern __shared__ char smem[];
    const uint32_t sb = smem_u32(smem);
    const int tid = threadIdx.x, wid = tid >> 5, lid = tid & 31;
    const int side = blockIdx.y;
    const int rowBase = blockIdx.x * BM;
    const float* __restrict__ A = side ? A1 : A0;

    const int wm = wid >> 2, wn = wid & 3;       // warp grid 2 x 4
    const int g = lid >> 3, lr = lid & 7;
    const int lrow = (g & 1) * 8 + lr;           // ldmatrix row within 16-frag
    const int lk   = (g >> 1) * 8;               // ldmatrix k offset within 16

    float acc[2][4][4];
    #pragma unroll
    for (int i = 0; i < 2; ++i)
        #pragma unroll
        for (int j = 0; j < 4; ++j)
            #pragma unroll
            for (int q = 0; q < 4; ++q) acc[i][j][q] = 0.f;

    // A loader: thread covers row=tid/4 (0..63), k-quarter=tid%4 (8 floats)
    const int arow = tid >> 2, aq = tid & 3;
    const float* agp = A + (size_t)(rowBase + arow) * KD + aq * 8;
    // B loader: thread covers row=tid/2 (0..127), k-half=tid%2 (16 halfs)
    const int bn = tid >> 1, bq = tid & 1;
    const __half* bgp = g_wt_hi + (size_t)bn * KPAD + bq * 16;
    const uint32_t bdst0 = sb + BHI_OFF + (uint32_t)bn * RS * 2 + bq * 32;

    float4 ap0, ap1;

    for (int c = 0; c < NCHUNK; ++c) {
        const int k0 = c * BK;
        const uint32_t stg_off = (uint32_t)(c & 1) * STAGE_BYTES;

        const int kb = k0 + aq * 8;
        ap0 = (kb < KD)     ? *(const float4*)(agp + k0)
                            : make_float4(0.f, 0.f, 0.f, 0.f);
        ap1 = (kb + 4 < KD) ? *(const float4*)(agp + k0 + 4)
                            : make_float4(0.f, 0.f, 0.f, 0.f);

        cp_async16(bdst0 + stg_off,      bgp + k0);
        cp_async16(bdst0 + stg_off + 16, bgp + k0 + 8);
        cp_commit();

        if (c > 0) compute_stage(sb + (uint32_t)((c - 1) & 1) * STAGE_BYTES,
                                 wm, wn, lrow, lk, acc);

        {
            const uint32_t off = stg_off + AHI_OFF
                               + ((uint32_t)arow * RS + aq * 8) * 2;
            __half2 h01 = __floats2half2_rn(ap0.x, ap0.y);
            __half2 h23 = __floats2half2_rn(ap0.z, ap0.w);
            __half2 h45 = __floats2half2_rn(ap1.x, ap1.y);
            __half2 h67 = __floats2half2_rn(ap1.z, ap1.w);
            __half2 l01 = __floats2half2_rn(ap0.x - __low2float(h01),
                                            ap0.y - __high2float(h01));
            __half2 l23 = __floats2half2_rn(ap0.z - __low2float(h23),
                                            ap0.w - __high2float(h23));
            __half2 l45 = __floats2half2_rn(ap1.x - __low2float(h45),
                                            ap1.y - __high2float(h45));
            __half2 l67 = __floats2half2_rn(ap1.z - __low2float(h67),
                                            ap1.w - __high2float(h67));
            *(uint4*)(smem + off) = make_uint4(
                *(uint32_t*)&h01, *(uint32_t*)&h23,
                *(uint32_t*)&h45, *(uint32_t*)&h67);
            *(uint4*)(smem + off + (ALO_OFF - AHI_OFF)) = make_uint4(
                *(uint32_t*)&l01, *(uint32_t*)&l23,
                *(uint32_t*)&l45, *(uint32_t*)&l67);
        }
        cp_wait0();
        __syncthreads();
    }
    compute_stage(sb + (uint32_t)((NCHUNK - 1) & 1) * STAGE_BYTES,
                  wm, wn, lrow, lk, acc);

    // Epilogue: bias + ReLU -> global; column sums -> g_mean (fused mean)
    const int trow = lid >> 2, tcol = (lid & 3) * 2;
    float bcol[4][2];
    #pragma unroll
    for (int nf = 0; nf < 4; ++nf) {
        bcol[nf][0] = __ldg(bias + wn * 32 + nf * 8 + tcol);
        bcol[nf][1] = __ldg(bias + wn * 32 + nf * 8 + tcol + 1);
    }
    float cs[4][2];
    #pragma unroll
    for (int nf = 0; nf < 4; ++nf) { cs[nf][0] = 0.f; cs[nf][1] = 0.f; }

    float* Cb = g_t[side];
    #pragma unroll
    for (int mf = 0; mf < 2; ++mf) {
        const int r0 = rowBase + wm * 32 + mf * 16 + trow;
        #pragma unroll
        for (int nf = 0; nf < 4; ++nf) {
            const int c0 = wn * 32 + nf * 8 + tcol;
            float2 v0, v1;
            v0.x = fmaxf(acc[mf][nf][0] + bcol[nf][0], 0.f);
            v0.y = fmaxf(acc[mf][nf][1] + bcol[nf][1], 0.f);
            v1.x = fmaxf(acc[mf][nf][2] + bcol[nf][0], 0.f);
            v1.y = fmaxf(acc[mf][nf][3] + bcol[nf][1], 0.f);
            *(float2*)(Cb + (size_t)r0 * ND + c0)       = v0;
            *(float2*)(Cb + (size_t)(r0 + 8) * ND + c0) = v1;
            cs[nf][0] += v0.x + v1.x;
            cs[nf][1] += v0.y + v1.y;
        }
    }
    #pragma unroll
    for (int o = 4; o <= 16; o <<= 1)
        #pragma unroll
        for (int nf = 0; nf < 4; ++nf) {
            cs[nf][0] += __shfl_xor_sync(0xffffffffu, cs[nf][0], o);
            cs[nf][1] += __shfl_xor_sync(0xffffffffu, cs[nf][1], o);
        }
    if (lid < 4) {
        const int b = blockIdx.x / (MTOK / BM);   // 20 M-tiles per sample
        float* mptr = g_mean[side] + b * ND + wn * 32;
        #pragma unroll
        for (int nf = 0; nf < 4; ++nf) {
            atomicAdd(mptr + nf * 8 + tcol,     cs[nf][0]);
            atomicAdd(mptr + nf * 8 + tcol + 1, cs[nf][1]);
        }
    }
}

// ---------------------------------------------------------------------------
// Kernel 2: attention per review — two coalesced float4 passes over g_t.
// Grid (320, 2), 128 threads.
// ---------------------------------------------------------------------------
__global__ __launch_bounds__(128) void attn_kernel(
    const int* __restrict__ mask_a, const int* __restrict__ mask_b,
    float* __restrict__ out)
{
    __shared__ __align__(16) float meanv[128];
    __shared__ __align__(16) float part[4][128];
    __shared__ float sc[128], wv[128], red[8];

    const int side = blockIdx.y;
    const int n    = blockIdx.x;
    const int b    = n / RV_NUM;
    const int tid  = threadIdx.x;
    const int lane = tid & 31, w = tid >> 5;

    const float* __restrict__ T = g_t[side] + (size_t)n * RV_LEN * ND;
    const int*   __restrict__ mask = side ? mask_b : mask_a;

    meanv[tid] = g_mean[side ^ 1][b * ND + tid] * (1.0f / (float)MTOK);
    __syncthreads();

    const float4 mv = *(const float4*)&meanv[lane * 4];

    // Pass 1: scores. Warp w covers tokens [w*32, w*32+32); lanes split the row.
    #pragma unroll 8
    for (int t = 0; t < 32; ++t) {
        const int l = w * 32 + t;
        float4 x = *(const float4*)(T + (size_t)l * ND + lane * 4);
        float p = x.x * mv.x + x.y * mv.y + x.z * mv.z + x.w * mv.w;
        #pragma unroll
        for (int o = 16; o; o >>= 1) p += __shfl_xor_sync(0xffffffffu, p, o);
        if (lane == 0) sc[l] = p;
    }
    __syncthreads();

    // Masked softmax over this review's 128 tokens (thread = token).
    float logit = (mask[n * RV_LEN + tid] > 0) ? sc[tid] : -1e9f;
    float v = logit;
    #pragma unroll
    for (int o = 16; o; o >>= 1) v = fmaxf(v, __shfl_xor_sync(0xffffffffu, v, o));
    if (lane == 0) red[w] = v;
    __syncthreads();
    const float gmax = fmaxf(fmaxf(red[0], red[1]), fmaxf(red[2], red[3]));

    const float e = __expf(logit - gmax);
    v = e;
    #pragma unroll
    for (int o = 16; o; o >>= 1) v += __shfl_xor_sync(0xffffffffu, v, o);
    if (lane == 0) red[4 + w] = v;
    __syncthreads();
    const float gsum = red[4] + red[5] + red[6] + red[7];

    const float wgt = e / gsum;
    wv[tid] = wgt;
    out[(size_t)(2 + side) * ROWS + (size_t)n * RV_LEN + tid] = wgt;
    __syncthreads();

    // Pass 2: weighted sum. Row-group w handles rows l ≡ w (mod 4), lanes split d.
    float4 acc = make_float4(0.f, 0.f, 0.f, 0.f);
    #pragma unroll 8
    for (int l = w; l < RV_LEN; l += 4) {
        float4 x = *(const float4*)(T + (size_t)l * ND + lane * 4);
        const float wl = wv[l];
        acc.x += wl * x.x; acc.y += wl * x.y;
        acc.z += wl * x.z; acc.w += wl * x.w;
    }
    *(float4*)&part[w][lane * 4] = acc;
    __syncthreads();
    float s = part[0][tid] + part[1][tid] + part[2][tid] + part[3][tid];
    out[(size_t)side * ROWS + (size_t)n * ND + tid] = s;
}

// ---------------------------------------------------------------------------
extern "C" void kernel_launch(void* const* d_in, const int* in_sizes, int n_in,
                              void* d_out, int out_size)
{
    const float* seq_a  = (const float*)d_in[0];
    const float* seq_b  = (const float*)d_in[1];
    const int*   mask_a = (const int*)d_in[2];
    const int*   mask_b = (const int*)d_in[3];
    const float* W      = (const float*)d_in[4];
    const float* bias   = (const float*)d_in[5];
    float* out = (float*)d_out;

    cudaFuncSetAttribute(gemm_mma_kernel, cudaFuncAttributeMaxDynamicSharedMemorySize, GEMM_SMEM);

    prep_w_kernel<<<160, 256>>>(W);

    dim3 g1(ROWS / BM, 2);
    gemm_mma_kernel<<<g1, 256, GEMM_SMEM>>>(seq_a, seq_b, bias);

    dim3 g3(NREV, 2);
    attn_kernel<<<g3, 128>>>(mask_a, mask_b, out);
}